// round 17
// baseline (speedup 1.0000x reference)
#include <cuda_runtime.h>
#include <cuda_bf16.h>
#include <cstdint>

// ---------------------------------------------------------------------------
// Convolution_29738353557732 : e3nn-style graph conv
// R17: warp-autonomous k_edge — 768-thr CTA (24 warps/SM), zero in-loop
//      barriers, per-warp 6-edge groups, reg-resident w1 columns.
// ---------------------------------------------------------------------------

#define NMAX 50176
typedef unsigned long long ull;

__device__ float g_f  [NMAX * 160];
__device__ float g_sc [NMAX * 160];
__device__ float g_mid[NMAX * 384];

__device__ __forceinline__ void red4(float* p, float a, float b, float c, float d) {
    asm volatile("red.global.add.v4.f32 [%0], {%1,%2,%3,%4};"
                 :: "l"(p), "f"(a), "f"(b), "f"(c), "f"(d) : "memory");
}
__device__ __forceinline__ ull fdup(float x) {
    ull r; asm("mov.b64 %0, {%1, %1};" : "=l"(r) : "f"(x)); return r;
}
__device__ __forceinline__ void ffma2(ull& acc, ull a, ull b) {
    asm("fma.rn.f32x2 %0, %1, %2, %0;" : "+l"(acc) : "l"(a), "l"(b));
}
__device__ __forceinline__ float2 funpack(ull p) {
    float lo, hi; asm("mov.b64 {%0, %1}, %2;" : "=f"(lo), "=f"(hi) : "l"(p));
    return make_float2(lo, hi);
}

__global__ void k_dummy() {}

// ---------------------------------------------------------------- node pre
// 2 nodes per warp (proven). Also zeroes g_mid.
#define PRE_SCW0 0
#define PRE_L1W0 16384
#define PRE_SCW1 32768
#define PRE_L1W1 36864
#define PRE_X    40960
#define PRE_SMEM 51200

__global__ __launch_bounds__(256) void k_nodepre(
    const float* __restrict__ x, const float* __restrict__ attr,
    const float* __restrict__ sc_w0, const float* __restrict__ sc_w1,
    const float* __restrict__ l1w0, const float* __restrict__ l1w1, int N)
{
    extern __shared__ unsigned char sbp[];
    float* s_scw0 = (float*)(sbp + PRE_SCW0);
    float* s_l1w0 = (float*)(sbp + PRE_L1W0);
    float* s_scw1 = (float*)(sbp + PRE_SCW1);
    float* s_l1w1 = (float*)(sbp + PRE_L1W1);
    float* s_x    = (float*)(sbp + PRE_X);     // 16 rows x 160

    {   // zero g_mid (grid-stride)
        float4* m4 = reinterpret_cast<float4*>(g_mid);
        int tot = N * 96;
        int stride = gridDim.x * 256;
        for (int i = blockIdx.x * 256 + threadIdx.x; i < tot; i += stride)
            m4[i] = make_float4(0.f, 0.f, 0.f, 0.f);
    }

    for (int i = threadIdx.x; i < 4096; i += 256) { s_scw0[i] = sc_w0[i]; s_l1w0[i] = l1w0[i]; }
    for (int i = threadIdx.x; i < 1024; i += 256) { s_scw1[i] = sc_w1[i]; s_l1w1[i] = l1w1[i]; }

    int wrp = threadIdx.x >> 5, l = threadIdx.x & 31;
    int n0 = blockIdx.x * 16 + wrp * 2;
    int n1 = n0 + 1;
    bool v0 = n0 < N, v1 = n1 < N;
    float* xr0 = &s_x[(wrp * 2) * 160];
    float* xr1 = &s_x[(wrp * 2 + 1) * 160];
    if (v0) {
#pragma unroll
        for (int i = 0; i < 5; i++) xr0[l + 32 * i] = x[(size_t)n0 * 160 + l + 32 * i];
    }
    if (v1) {
#pragma unroll
        for (int i = 0; i < 5; i++) xr1[l + 32 * i] = x[(size_t)n1 * 160 + l + 32 * i];
    }
    __syncthreads();
    if (!v0) return;

    float a0 = attr[n0];
    float a1 = v1 ? attr[n1] : 0.f;
    int w_[3], d_[3];
#pragma unroll
    for (int i = 0; i < 3; i++) { int o = l + 32 * i; w_[i] = o / 3; d_[i] = o - 3 * w_[i]; }

    ull af0 = 0ull, as0 = 0ull, af1 = 0ull, as1 = 0ull;
#pragma unroll 8
    for (int u = 0; u < 64; u++) {
        ull wl = *(const ull*)&s_l1w0[u * 64 + 2 * l];
        ull ws = *(const ull*)&s_scw0[u * 64 + 2 * l];
        ull x0 = fdup(xr0[u]);
        ull x1 = fdup(xr1[u]);
        ffma2(af0, x0, wl); ffma2(as0, x0, ws);
        ffma2(af1, x1, wl); ffma2(as1, x1, ws);
    }
    float fv0[3] = {0,0,0}, sv0[3] = {0,0,0}, fv1[3] = {0,0,0}, sv1[3] = {0,0,0};
#pragma unroll 4
    for (int u = 0; u < 32; u++) {
#pragma unroll
        for (int i = 0; i < 3; i++) {
            float wl = s_l1w1[u * 32 + w_[i]];
            float ws = s_scw1[u * 32 + w_[i]];
            float xv0 = xr0[64 + 3 * u + d_[i]];
            float xv1 = xr1[64 + 3 * u + d_[i]];
            fv0[i] += xv0 * wl;  sv0[i] += xv0 * ws;
            fv1[i] += xv1 * wl;  sv1[i] += xv1 * ws;
        }
    }
    {
        float* fo = &g_f[(size_t)n0 * 160];
        float* so = &g_sc[(size_t)n0 * 160];
        float S1 = 0.125f * a0, S2 = 0.17677669529663687f * a0;
        float2 ff = funpack(af0), ss = funpack(as0);
        *(float2*)&fo[2 * l] = make_float2(ff.x * S1, ff.y * S1);
        *(float2*)&so[2 * l] = make_float2(ss.x * S1, ss.y * S1);
#pragma unroll
        for (int i = 0; i < 3; i++) {
            fo[64 + l + 32 * i] = fv0[i] * S2;
            so[64 + l + 32 * i] = sv0[i] * S2;
        }
    }
    if (v1) {
        float* fo = &g_f[(size_t)n1 * 160];
        float* so = &g_sc[(size_t)n1 * 160];
        float S1 = 0.125f * a1, S2 = 0.17677669529663687f * a1;
        float2 ff = funpack(af1), ss = funpack(as1);
        *(float2*)&fo[2 * l] = make_float2(ff.x * S1, ff.y * S1);
        *(float2*)&so[2 * l] = make_float2(ss.x * S1, ss.y * S1);
#pragma unroll
        for (int i = 0; i < 3; i++) {
            fo[64 + l + 32 * i] = fv1[i] * S2;
            so[64 + l + 32 * i] = sv1[i] * S2;
        }
    }
}

// ---------------------------------------------------------------- edge kernel
// 768 threads (24 warps), 1 CTA/SM, warp-autonomous: each warp owns 6-edge
// groups, zero block barriers in the loop.
// smem: [w2 49152][w1t 2048][per-warp 7168 x 24]
//   per-warp: wt 4608 | h 1536 (j-major stride 6) | g 640 | es 192 | ea 96
//             | src 24 | dst 24 | pad
#define EW_W2   0
#define EW_W1T  49152
#define EW_PW   51200
#define PW_SZ   7168
#define PW_WT   0
#define PW_H    4608
#define PW_G    6144
#define PW_ES   6784
#define PW_EA   6976
#define PW_SRC  7072
#define PW_DST  7096
#define K17_SMEM (EW_PW + 24 * PW_SZ)   // 223232

__global__ __launch_bounds__(768, 1) void k_edge(
    const float* __restrict__ edge_attr, const float* __restrict__ edge_scalars,
    const float* __restrict__ fc_w1, const float* __restrict__ fc_w2,
    const int* __restrict__ edge_src, const int* __restrict__ edge_dst, int E)
{
    extern __shared__ unsigned char sb[];
    float* s_w2  = (float*)(sb + EW_W2);
    float* s_w1t = (float*)(sb + EW_W1T);

    const int tid = threadIdx.x;
    const int wrp = tid >> 5, l = tid & 31;

    unsigned char* pw = sb + EW_PW + wrp * PW_SZ;
    float*  s_wt  = (float*)(pw + PW_WT);
    float*  s_hw  = (float*)(pw + PW_H);
    float*  s_g   = (float*)(pw + PW_G);
    float*  s_es  = (float*)(pw + PW_ES);
    float4* s_ea4 = (float4*)(pw + PW_EA);
    int*    s_src = (int*)(pw + PW_SRC);
    int*    s_dst = (int*)(pw + PW_DST);

    for (int i = tid; i < 512; i += 768) {
        int c = i >> 6, j = i & 63;            // w1t[j*8+c] = fc_w1[c*64+j]
        s_w1t[j * 8 + c] = fc_w1[i];
    }
    for (int i = tid; i < 12288; i += 768) s_w2[i] = fc_w2[i] * 0.125f;
    __syncthreads();                            // the only block barrier

    // register-resident w1 columns for j=l and j=32+l
    const float4 w1aA = *(const float4*)&s_w1t[l * 8];
    const float4 w1aB = *(const float4*)&s_w1t[l * 8 + 4];
    const float4 w1bA = *(const float4*)&s_w1t[(32 + l) * 8];
    const float4 w1bB = *(const float4*)&s_w1t[(32 + l) * 8 + 4];

    const int ngroups = (E + 5) / 6;
    const int gstride = gridDim.x * 24;

    for (int g = blockIdx.x * 24 + wrp; g < ngroups; g += gstride) {
        const int e0 = g * 6;

        // ---- stage (warp-local)
        if (l < 12) {
            int e = l >> 1, h = l & 1, ge = e0 + e;
            float4 v = make_float4(0.f, 0.f, 0.f, 0.f);
            if (ge < E) v = *(const float4*)&edge_scalars[(size_t)ge * 8 + 4 * h];
            *(float4*)&s_es[e * 8 + 4 * h] = v;
        } else if (l < 18) {
            int e = l - 12, ge = e0 + e;
            s_ea4[e] = (ge < E) ? *(const float4*)&edge_attr[(size_t)ge * 4]
                                : make_float4(0.f, 0.f, 0.f, 0.f);
        } else if (l < 24) {
            int e = l - 18, ge = e0 + e;
            s_src[e] = (ge < E) ? edge_src[ge] : 0;
        } else if (l < 30) {
            int e = l - 24, ge = e0 + e;
            s_dst[e] = (ge < E) ? edge_dst[ge] : 0;
        }
        __syncwarp();

        // ---- phase 1: h for this warp's 6 edges at j=l and j=32+l
#pragma unroll
        for (int e = 0; e < 6; e++) {
            float4 A = *(const float4*)&s_es[e * 8];
            float4 B = *(const float4*)&s_es[e * 8 + 4];
            float aA = A.x * w1aA.x + A.y * w1aA.y + A.z * w1aA.z + A.w * w1aA.w
                     + B.x * w1aB.x + B.y * w1aB.y + B.z * w1aB.z + B.w * w1aB.w;
            float aB = A.x * w1bA.x + A.y * w1bA.y + A.z * w1bA.z + A.w * w1bA.w
                     + B.x * w1bB.x + B.y * w1bB.y + B.z * w1bB.z + B.w * w1bB.w;
            aA *= 0.3535533905932738f;
            aB *= 0.3535533905932738f;
            s_hw[l * 6 + e]        = __fdividef(aA, 1.f + __expf(-aA));
            s_hw[(32 + l) * 6 + e] = __fdividef(aB, 1.f + __expf(-aB));
        }
        __syncwarp();

        // ---- phase 2: wt = h @ (0.125*w2); 6 edges x 192 outs
        {
            ull acc[6][3];
#pragma unroll
            for (int a = 0; a < 6; a++)
#pragma unroll
                for (int b = 0; b < 3; b++) acc[a][b] = 0ull;

#pragma unroll 4
            for (int j = 0; j < 64; j++) {
                const float2* hp = (const float2*)&s_hw[j * 6];
                float2 h01 = hp[0], h23 = hp[1], h45 = hp[2];
                ull hd[6];
                hd[0] = fdup(h01.x); hd[1] = fdup(h01.y);
                hd[2] = fdup(h23.x); hd[3] = fdup(h23.y);
                hd[4] = fdup(h45.x); hd[5] = fdup(h45.y);
                const ull* wp = (const ull*)&s_w2[j * 192 + 2 * l];
                ull w0 = wp[0], w1v = wp[32], w2v = wp[64];
#pragma unroll
                for (int e = 0; e < 6; e++) {
                    ffma2(acc[e][0], hd[e], w0);
                    ffma2(acc[e][1], hd[e], w1v);
                    ffma2(acc[e][2], hd[e], w2v);
                }
            }
#pragma unroll
            for (int e = 0; e < 6; e++) {
                ull* outp = (ull*)&s_wt[e * 192 + 2 * l];
                outp[0]  = acc[e][0];
                outp[32] = acc[e][1];
                outp[64] = acc[e][2];
            }
        }
        __syncwarp();

        // ---- phase 3: prefetched gather + features + red.v4 scatter
        {
            float* gw = s_g;
            float4* gw4 = (float4*)gw;

            float4 pa, pb;
            {
                const float4* fr = (const float4*)&g_f[(size_t)s_src[0] * 160];
                pa = fr[l];
                pb = (l < 8) ? fr[32 + l] : make_float4(0.f, 0.f, 0.f, 0.f);
            }

#pragma unroll
            for (int e = 0; e < 6; e++) {
                const bool valid = (e0 + e) < E;

                gw4[l] = pa;
                if (l < 8) gw4[32 + l] = pb;
                if (e < 5) {
                    const float4* fr = (const float4*)&g_f[(size_t)s_src[e + 1] * 160];
                    pa = fr[l];
                    if (l < 8) pb = fr[32 + l];
                }
                __syncwarp();

                float4 ea = s_ea4[e];
                const float ys = ea.x, yv0 = ea.y, yv1 = ea.z, yv2 = ea.w;
                const float* wt = &s_wt[e * 192];
                float* mb = &g_mid[(size_t)s_dst[e] * 384];

#pragma unroll
                for (int i = 0; i < 3; i++) {
                    const int t0 = i * 128 + 4 * l;
                    float v[4];
                    if (t0 < 64) {                       // m0a
#pragma unroll
                        for (int j = 0; j < 4; j++) v[j] = gw[t0 + j] * ys * wt[t0 + j];
                    } else if (t0 < 96) {                // m0b
                        const int c0 = t0 - 64;
#pragma unroll
                        for (int j = 0; j < 4; j++) {
                            int c = c0 + j;
                            float dot = gw[64 + 3 * c] * yv0 + gw[65 + 3 * c] * yv1
                                      + gw[66 + 3 * c] * yv2;
                            v[j] = dot * 0.5773502691896258f * wt[160 + c];
                        }
                    } else if (t0 < 288) {               // m1a
                        const int s0 = t0 - 96;
#pragma unroll
                        for (int j = 0; j < 4; j++) {
                            int s = s0 + j;
                            int u = s / 3, d = s - 3 * u;
                            float yvd = (d == 0) ? yv0 : ((d == 1) ? yv1 : yv2);
                            v[j] = gw[u] * yvd * wt[64 + u];
                        }
                    } else {                             // m1b
                        const int s0 = t0 - 288;
#pragma unroll
                        for (int j = 0; j < 4; j++) {
                            int s = s0 + j;
                            int u = s / 3;
                            v[j] = gw[64 + s] * ys * wt[128 + u];
                        }
                    }
                    if (valid) red4(&mb[t0], v[0], v[1], v[2], v[3]);
                }
                __syncwarp();
            }
        }
        __syncwarp();
    }
}

// ---------------------------------------------------------------- node post
// 2 nodes per warp; float4 mid loads; vector part lane=w.
#define PST_W0  0
#define PST_W1  24576
#define PST_L3  36864
#define PST_MID 37376
#define PST_SMEM 61952

__global__ __launch_bounds__(256) void k_nodepost(
    const float* __restrict__ attr, const float* __restrict__ l2w0,
    const float* __restrict__ l2w1, const float* __restrict__ l3,
    const int* __restrict__ nn, float* __restrict__ out, int N)
{
    extern __shared__ unsigned char sbq[];
    float* s_w0  = (float*)(sbq + PST_W0);
    float* s_w1  = (float*)(sbq + PST_W1);
    float* s_l3  = (float*)(sbq + PST_L3);
    float* s_mid = (float*)(sbq + PST_MID);   // 16 rows x 384

    for (int i = threadIdx.x; i < 6144; i += 256) s_w0[i] = l2w0[i];
    for (int i = threadIdx.x; i < 3072; i += 256) s_w1[i] = l2w1[i];
    if (threadIdx.x < 96) s_l3[threadIdx.x] = l3[threadIdx.x];

    float ms = rsqrtf((float)nn[0]);
    const float SC = 0.10206207261596575f;
    int wrp = threadIdx.x >> 5, l = threadIdx.x & 31;
    int n0 = blockIdx.x * 16 + wrp * 2;
    int n1 = n0 + 1;
    bool v0 = n0 < N, v1 = n1 < N;
    float* mr0 = &s_mid[(wrp * 2) * 384];
    float* mr1 = &s_mid[(wrp * 2 + 1) * 384];
    if (v0) {
        const float4* m4 = (const float4*)&g_mid[(size_t)n0 * 384];
        float4* s4 = (float4*)mr0;
#pragma unroll
        for (int i = 0; i < 3; i++) s4[l + 32 * i] = m4[l + 32 * i];
    }
    if (v1) {
        const float4* m4 = (const float4*)&g_mid[(size_t)n1 * 384];
        float4* s4 = (float4*)mr1;
#pragma unroll
        for (int i = 0; i < 3; i++) s4[l + 32 * i] = m4[l + 32 * i];
    }
    __syncthreads();
    if (!v0) return;

    float a0 = attr[n0];
    float a1 = v1 ? attr[n1] : 0.f;

    ull c0 = 0ull, c1 = 0ull;
    float ang0 = 0.f, ang1 = 0.f;
#pragma unroll 8
    for (int u = 0; u < 96; u++) {
        ull w = *(const ull*)&s_w0[u * 64 + 2 * l];
        float m0 = mr0[u], m1 = mr1[u];
        ffma2(c0, fdup(m0), w);
        ffma2(c1, fdup(m1), w);
        float lw = s_l3[u];
        ang0 += m0 * lw;
        ang1 += m1 * lw;
    }
    // vector part: lane l owns output w=l, all 3 d components
    float cv0[3] = {0,0,0}, cv1[3] = {0,0,0};
#pragma unroll 4
    for (int u = 0; u < 96; u++) {
        float w = s_w1[u * 32 + l];
#pragma unroll
        for (int d = 0; d < 3; d++) {
            cv0[d] += mr0[96 + 3 * u + d] * w;
            cv1[d] += mr1[96 + 3 * u + d] * w;
        }
    }
    {
        float sA = SC * ms * a0;
        float angle = 0.1f * ang0 * sA;
        float sa, ca; sincosf(angle, &sa, &ca);
        const float* scrow = &g_sc[(size_t)n0 * 160];
        float* orow = &out[(size_t)n0 * 160];
        float2 cc = funpack(c0);
        float2 sc2 = *(const float2*)&scrow[2 * l];
        *(float2*)&orow[2 * l] = make_float2(ca * sc2.x + sa * (cc.x * sA),
                                             ca * sc2.y + sa * (cc.y * sA));
#pragma unroll
        for (int d = 0; d < 3; d++)
            orow[64 + 3 * l + d] = ca * scrow[64 + 3 * l + d] + sa * (cv0[d] * sA);
    }
    if (v1) {
        float sA = SC * ms * a1;
        float angle = 0.1f * ang1 * sA;
        float sa, ca; sincosf(angle, &sa, &ca);
        const float* scrow = &g_sc[(size_t)n1 * 160];
        float* orow = &out[(size_t)n1 * 160];
        float2 cc = funpack(c1);
        float2 sc2 = *(const float2*)&scrow[2 * l];
        *(float2*)&orow[2 * l] = make_float2(ca * sc2.x + sa * (cc.x * sA),
                                             ca * sc2.y + sa * (cc.y * sA));
#pragma unroll
        for (int d = 0; d < 3; d++)
            orow[64 + 3 * l + d] = ca * scrow[64 + 3 * l + d] + sa * (cv1[d] * sA);
    }
}

// ---------------------------------------------------------------- launch
extern "C" void kernel_launch(void* const* d_in, const int* in_sizes, int n_in,
                              void* d_out, int out_size)
{
    const float* node_input   = (const float*)d_in[0];
    const float* node_attr    = (const float*)d_in[1];
    const float* edge_attr    = (const float*)d_in[2];
    const float* edge_scalars = (const float*)d_in[3];
    const float* sc_w0        = (const float*)d_in[4];
    const float* sc_w1        = (const float*)d_in[5];
    const float* lin1_w0      = (const float*)d_in[6];
    const float* lin1_w1      = (const float*)d_in[7];
    const float* fc_w1        = (const float*)d_in[8];
    const float* fc_w2        = (const float*)d_in[9];
    const float* lin2_w0      = (const float*)d_in[10];
    const float* lin2_w1      = (const float*)d_in[11];
    const float* lin3_w       = (const float*)d_in[12];
    const int*   edge_src     = (const int*)d_in[13];
    const int*   edge_dst     = (const int*)d_in[14];
    const int*   num_neigh    = (const int*)d_in[15];
    float* out = (float*)d_out;

    int N = in_sizes[0] / 160;
    int E = in_sizes[2] / 4;

    cudaFuncSetAttribute(k_nodepre, cudaFuncAttributeMaxDynamicSharedMemorySize, PRE_SMEM);
    k_nodepre<<<(N + 15) / 16, 256, PRE_SMEM>>>(node_input, node_attr, sc_w0, sc_w1,
                                                lin1_w0, lin1_w1, N);

    // dummy launch keeps the 4-launch pattern (profiling slot rotation)
    k_dummy<<<1, 32>>>();

    cudaFuncSetAttribute(k_edge, cudaFuncAttributeMaxDynamicSharedMemorySize, K17_SMEM);
    k_edge<<<148, 768, K17_SMEM>>>(edge_attr, edge_scalars, fc_w1, fc_w2,
                                   edge_src, edge_dst, E);

    cudaFuncSetAttribute(k_nodepost, cudaFuncAttributeMaxDynamicSharedMemorySize, PST_SMEM);
    k_nodepost<<<(N + 15) / 16, 256, PST_SMEM>>>(node_attr, lin2_w0, lin2_w1, lin3_w,
                                                 num_neigh, out, N);
}